// round 13
// baseline (speedup 1.0000x reference)
#include <cuda_runtime.h>
#include <cuda_fp16.h>
#include <math.h>
#include <cstdint>

#define BATCH 2
#define SEQ   2048
#define HID   2048
#define NHEAD 16
#define HDIM  128
#define FFD   8192
#define ROWS  (BATCH*SEQ)   // 4096
#define QKVLD (3*HID)       // 6144

// ---------------- scratch ---------------------------------------------------
__device__ __half g_qkv16[(size_t)ROWS*QKVLD];  // packed q|k|v (fp16)
__device__ float g_h [ROWS*HID];
__device__ __half g_xn16[ROWS*HID];
__device__ __half g_att16[ROWS*HID];
__device__ __half g_hn16[ROWS*HID];
__device__ __half g_ff16[(size_t)ROWS*FFD];
__device__ __half g_wqkv16[(size_t)HID*QKVLD];
__device__ __half g_wo16[HID*HID];
__device__ __half g_win16[(size_t)HID*FFD];
__device__ __half g_wout16[(size_t)HID*FFD];

// ============================ helpers ========================================
__device__ __forceinline__ uint32_t smem_u32(const void* p) {
    uint32_t a;
    asm("{ .reg .u64 t; cvta.to.shared.u64 t, %1; cvt.u32.u64 %0, t; }"
        : "=r"(a) : "l"(p));
    return a;
}
__device__ __forceinline__ void cp16(uint32_t dst, const void* src) {
    asm volatile("cp.async.cg.shared.global [%0], [%1], 16;" :: "r"(dst), "l"(src));
}
__device__ __forceinline__ void cp_commit() { asm volatile("cp.async.commit_group;"); }
template<int N> __device__ __forceinline__ void cp_wait() {
    asm volatile("cp.async.wait_group %0;" :: "n"(N));
}
__device__ __forceinline__ void ldsm_x4(uint32_t* r, uint32_t addr) {
    asm volatile("ldmatrix.sync.aligned.m8n8.x4.shared.b16 {%0,%1,%2,%3}, [%4];"
        : "=r"(r[0]), "=r"(r[1]), "=r"(r[2]), "=r"(r[3]) : "r"(addr));
}
__device__ __forceinline__ void ldsm_x4_t(uint32_t* r, uint32_t addr) {
    asm volatile("ldmatrix.sync.aligned.m8n8.x4.trans.shared.b16 {%0,%1,%2,%3}, [%4];"
        : "=r"(r[0]), "=r"(r[1]), "=r"(r[2]), "=r"(r[3]) : "r"(addr));
}
__device__ __forceinline__ void mma_f16(float* c, const uint32_t* a, const uint32_t* b) {
    asm volatile("mma.sync.aligned.m16n8k16.row.col.f32.f16.f16.f32 "
        "{%0,%1,%2,%3}, {%4,%5,%6,%7}, {%8,%9}, {%0,%1,%2,%3};"
        : "+f"(c[0]), "+f"(c[1]), "+f"(c[2]), "+f"(c[3])
        : "r"(a[0]), "r"(a[1]), "r"(a[2]), "r"(a[3]), "r"(b[0]), "r"(b[1]));
}
__device__ __forceinline__ void mma_f16_b(float* c, const uint32_t* a,
                                          uint32_t b0, uint32_t b1) {
    asm volatile("mma.sync.aligned.m16n8k16.row.col.f32.f16.f16.f32 "
        "{%0,%1,%2,%3}, {%4,%5,%6,%7}, {%8,%9}, {%0,%1,%2,%3};"
        : "+f"(c[0]), "+f"(c[1]), "+f"(c[2]), "+f"(c[3])
        : "r"(a[0]), "r"(a[1]), "r"(a[2]), "r"(a[3]), "r"(b0), "r"(b1));
}
__device__ __forceinline__ float gelu_tanh(float x) {
    float x3 = x * x * x;
    float t  = tanhf(0.7978845608028654f * (x + 0.044715f * x3));
    return 0.5f * x * (1.0f + t);
}
__device__ __forceinline__ uint32_t pack_h2(float x, float y) {
    __half2 h = __halves2half2(__float2half_rn(x), __float2half_rn(y));
    return *reinterpret_cast<uint32_t*>(&h);
}

// ============================================================================
// fp16 tensor-core GEMM, fp32 accumulate. BK=32, STG=4, cp_wait<2>.
// ACT: 0 -> fp16 C, 1 -> fp32 C + Res, 2 -> GELU -> fp16 C
// ============================================================================
#define BM 128
#define BN 128
#define BKH 32
#define LDAH 40
#define LDBH 136
#define ASZH (BM*LDAH)
#define BSZH (BKH*LDBH)
#define STG 4
#define STAGEH (ASZH + BSZH)        // 9472 halves
#define GEMM_SMEM (STG*STAGEH*2)    // 75776 bytes -> 2 CTAs/SM

template<int ACT>
__global__ __launch_bounds__(256, 2) void tc_gemm(
    const __half* __restrict__ A16,
    const __half* __restrict__ B16,
    const float* __restrict__ Res, float* __restrict__ Cf,
    __half* __restrict__ C16,
    int N_, int K)
{
    extern __shared__ __align__(16) __half smem[];

    const int tid  = threadIdx.x;
    const int wid  = tid >> 5;
    const int lane = tid & 31;
    const int gid  = lane >> 2;
    const int tg   = lane & 3;
    const int wm   = wid & 3;
    const int wn   = wid >> 2;
    const int bm = blockIdx.y * BM;
    const int bn = blockIdx.x * BN;
    const int nK = K / BKH;

    const int a_m = lane & 15;
    const int a_k = (lane >> 4) * 8;
    const int b_k = ((lane >> 3) & 1) * 8 + (lane & 7);
    const int b_n = (lane >> 4) * 8;

    auto load_stage = [&](int s, int kt) {
        const int k0 = kt * BKH;
        __half* As = smem + s*STAGEH;
        __half* Bs = As + ASZH;
        #pragma unroll
        for (int i = 0; i < 2; i++) {
            const int c  = tid + 256*i;
            const int ar = c >> 2, ak = (c & 3) << 3;
            cp16(smem_u32(&As[ar*LDAH + ak]), &A16[(size_t)(bm + ar)*K + k0 + ak]);
            const int bk = c >> 4, bnn = (c & 15) << 3;
            cp16(smem_u32(&Bs[bk*LDBH + bnn]), &B16[(size_t)(k0 + bk)*N_ + bn + bnn]);
        }
        cp_commit();
    };

    float acc[2][8][4];
    #pragma unroll
    for (int mt = 0; mt < 2; mt++)
        #pragma unroll
        for (int nt = 0; nt < 8; nt++)
            #pragma unroll
            for (int r = 0; r < 4; r++) acc[mt][nt][r] = 0.0f;

    #pragma unroll
    for (int s = 0; s < STG-1; s++) load_stage(s, s);

    for (int kt = 0; kt < nK; kt++) {
        cp_wait<STG-2>();
        __syncthreads();
        // refill stage (kt+3)%4 == (kt-1)%4: its readers finished before the
        // barrier (MMA register deps force ldsm completion pre-barrier).
        if (kt + STG - 1 < nK)
            load_stage((kt + STG - 1) % STG, kt + STG - 1);

        const int s = kt % STG;
        const __half* As = smem + s*STAGEH;
        const __half* Bs = As + ASZH;

        #pragma unroll
        for (int kk = 0; kk < 2; kk++) {
            uint32_t af[2][4];
            #pragma unroll
            for (int mt = 0; mt < 2; mt++) {
                const int mrow = wm*32 + mt*16 + a_m;
                const int koff = kk*16 + a_k;
                ldsm_x4(af[mt], smem_u32(&As[mrow*LDAH + koff]));
            }
            uint32_t bf[4][4];
            #pragma unroll
            for (int ng = 0; ng < 4; ng++) {
                const int koff = kk*16 + b_k;
                const int noff = wn*64 + ng*16 + b_n;
                ldsm_x4_t(bf[ng], smem_u32(&Bs[koff*LDBH + noff]));
            }
            #pragma unroll
            for (int mt = 0; mt < 2; mt++)
                #pragma unroll
                for (int nt = 0; nt < 8; nt++)
                    mma_f16(acc[mt][nt], af[mt], &bf[nt >> 1][(nt & 1) * 2]);
        }
    }

    #pragma unroll
    for (int mt = 0; mt < 2; mt++) {
        #pragma unroll
        for (int half_ = 0; half_ < 2; half_++) {
            const int r = bm + wm*32 + mt*16 + gid + half_*8;
            #pragma unroll
            for (int nt = 0; nt < 8; nt++) {
                const int cc = bn + wn*64 + nt*8 + tg*2;
                float v0 = acc[mt][nt][half_*2 + 0];
                float v1 = acc[mt][nt][half_*2 + 1];
                if (ACT == 0) {
                    *reinterpret_cast<__half2*>(&C16[(size_t)r*N_ + cc]) =
                        __halves2half2(__float2half_rn(v0), __float2half_rn(v1));
                } else if (ACT == 2) {
                    v0 = gelu_tanh(v0); v1 = gelu_tanh(v1);
                    *reinterpret_cast<__half2*>(&C16[(size_t)r*N_ + cc]) =
                        __halves2half2(__float2half_rn(v0), __float2half_rn(v1));
                } else {
                    const float2 rr = *reinterpret_cast<const float2*>(&Res[(size_t)r*N_ + cc]);
                    float2 o; o.x = v0 + rr.x; o.y = v1 + rr.y;
                    *reinterpret_cast<float2*>(&Cf[(size_t)r*N_ + cc]) = o;
                }
            }
        }
    }
}

// ------------- weight conversion: fp32 -> RN fp16 ---------------------------
__global__ void convqkv_kernel(const float* __restrict__ wq,
                               const float* __restrict__ wk,
                               const float* __restrict__ wv,
                               const float* __restrict__ wo,
                               __half* __restrict__ qkv16,
                               __half* __restrict__ wo16,
                               int n4)
{
    const int i = blockIdx.x*blockDim.x + threadIdx.x;
    if (i >= n4) return;
    const int y = blockIdx.y;
    const float* in = (y == 0) ? wq : (y == 1) ? wk : (y == 2) ? wv : wo;
    const int e   = i * 4;
    const int row = e >> 11;
    const int col = e & 2047;
    float4 v = reinterpret_cast<const float4*>(in)[i];
    __half2 p0 = __halves2half2(__float2half_rn(v.x), __float2half_rn(v.y));
    __half2 p1 = __halves2half2(__float2half_rn(v.z), __float2half_rn(v.w));
    __half* dst; size_t o;
    if (y < 3) { dst = qkv16; o = (size_t)row*QKVLD + y*HID + col; }
    else       { dst = wo16;  o = (size_t)row*HID + col; }
    reinterpret_cast<__half2*>(dst + o)[0] = p0;
    reinterpret_cast<__half2*>(dst + o)[1] = p1;
}
__global__ void conv2_kernel(const float* __restrict__ w0, __half* o0,
                             const float* __restrict__ w1, __half* o1,
                             int n4)
{
    const float* in = blockIdx.y ? w1 : w0;
    __half* dst = blockIdx.y ? o1 : o0;
    const int i = blockIdx.x*blockDim.x + threadIdx.x;
    if (i >= n4) return;
    float4 v = reinterpret_cast<const float4*>(in)[i];
    reinterpret_cast<__half2*>(dst)[2*i+0] =
        __halves2half2(__float2half_rn(v.x), __float2half_rn(v.y));
    reinterpret_cast<__half2*>(dst)[2*i+1] =
        __halves2half2(__float2half_rn(v.z), __float2half_rn(v.w));
}

// ---------------- LayerNorm -> fp16 output ----------------------------------
__global__ void ln_kernel(const float* __restrict__ x,
                          const float* __restrict__ g,
                          const float* __restrict__ b,
                          __half* __restrict__ o16)
{
    const int row = blockIdx.x;
    const int tid = threadIdx.x;
    const float* xr = x + (size_t)row * HID;

    float4 v0 = reinterpret_cast<const float4*>(xr)[tid];
    float4 v1 = reinterpret_cast<const float4*>(xr)[tid + 256];

    __shared__ float red[8];

    float s = v0.x+v0.y+v0.z+v0.w + v1.x+v1.y+v1.z+v1.w;
    #pragma unroll
    for (int o = 16; o > 0; o >>= 1) s += __shfl_xor_sync(0xffffffffu, s, o);
    if ((tid & 31) == 0) red[tid >> 5] = s;
    __syncthreads();
    float mu = (red[0]+red[1]+red[2]+red[3]+red[4]+red[5]+red[6]+red[7]) * (1.0f/HID);
    __syncthreads();

    float d0x=v0.x-mu, d0y=v0.y-mu, d0z=v0.z-mu, d0w=v0.w-mu;
    float d1x=v1.x-mu, d1y=v1.y-mu, d1z=v1.z-mu, d1w=v1.w-mu;
    float sq = d0x*d0x+d0y*d0y+d0z*d0z+d0w*d0w + d1x*d1x+d1y*d1y+d1z*d1z+d1w*d1w;
    #pragma unroll
    for (int o = 16; o > 0; o >>= 1) sq += __shfl_xor_sync(0xffffffffu, sq, o);
    if ((tid & 31) == 0) red[tid >> 5] = sq;
    __syncthreads();
    float var = (red[0]+red[1]+red[2]+red[3]+red[4]+red[5]+red[6]+red[7]) * (1.0f/HID);
    float rstd = rsqrtf(var + 1e-5f);

    float4 g0 = reinterpret_cast<const float4*>(g)[tid];
    float4 g1 = reinterpret_cast<const float4*>(g)[tid + 256];
    float4 b0 = reinterpret_cast<const float4*>(b)[tid];
    float4 b1 = reinterpret_cast<const float4*>(b)[tid + 256];

    const size_t base = (size_t)row * HID;
    reinterpret_cast<__half2*>(o16 + base)[tid*2+0] = __halves2half2(
        __float2half_rn(d0x*rstd*g0.x + b0.x), __float2half_rn(d0y*rstd*g0.y + b0.y));
    reinterpret_cast<__half2*>(o16 + base)[tid*2+1] = __halves2half2(
        __float2half_rn(d0z*rstd*g0.z + b0.z), __float2half_rn(d0w*rstd*g0.w + b0.w));
    reinterpret_cast<__half2*>(o16 + base)[(tid+256)*2+0] = __halves2half2(
        __float2half_rn(d1x*rstd*g1.x + b1.x), __float2half_rn(d1y*rstd*g1.y + b1.y));
    reinterpret_cast<__half2*>(o16 + base)[(tid+256)*2+1] = __halves2half2(
        __float2half_rn(d1z*rstd*g1.z + b1.z), __float2half_rn(d1w*rstd*g1.w + b1.w));
}

// ---------------- Flash attention: fp16 mma.sync, double-buffered K/V -------
#define FSTR 136
#define FLASH_SMEM (5*64*FSTR*2)   // Q + 2x(K,V): 87040 bytes -> 2 CTAs/SM

__global__ __launch_bounds__(128, 2) void flash_kernel(
    const __half* __restrict__ QKV,
    __half* __restrict__ O16)
{
    extern __shared__ __align__(16) __half fsm[];
    __half* Qs = fsm;
    // buffers: K[bi] at (1+2*bi), V[bi] at (2+2*bi)

    const int tid = threadIdx.x;
    const int w   = tid >> 5;
    const int lane = tid & 31;
    const int gid = lane >> 2;
    const int tg  = lane & 3;
    const int bh = blockIdx.y;
    const int b  = bh >> 4;
    const int h  = bh & 15;
    const int qb = blockIdx.x;
    const size_t rowbase = (size_t)b * SEQ;
    const int colbase = h * HDIM;
    const float scale = 0.088388347648318447f;

    const int a_r = lane & 15;
    const int a_c = (lane >> 4) * 8;
    const int t_k = ((lane >> 3) & 1) * 8 + (lane & 7);
    const int t_n = (lane >> 4) * 8;

    auto load_kv = [&](int bi, int kb) {
        __half* Ks = fsm + (1 + 2*bi)*64*FSTR;
        __half* Vs = fsm + (2 + 2*bi)*64*FSTR;
        #pragma unroll
        for (int it = 0; it < 8; ++it) {
            int idx = it*128 + tid;
            int r = idx >> 4;
            int c8 = (idx & 15) << 3;
            const size_t grow = (rowbase + kb*64 + r)*(size_t)QKVLD + colbase + c8;
            cp16(smem_u32(&Ks[r*FSTR + c8]), &QKV[grow + HID]);
            cp16(smem_u32(&Vs[r*FSTR + c8]), &QKV[grow + 2*HID]);
        }
    };

    // prologue: Q + K/V(0) in one group
    #pragma unroll
    for (int it = 0; it < 8; ++it) {
        int idx = it*128 + tid;
        int r = idx >> 4;
        int c8 = (idx & 15) << 3;
        cp16(smem_u32(&Qs[r*FSTR + c8]),
             &QKV[(rowbase + qb*64 + r)*(size_t)QKVLD + colbase + c8]);
    }
    load_kv(0, 0);
    cp_commit();

    float m0 = -1e30f, m1 = -1e30f, l0 = 0.0f, l1 = 0.0f;
    float oacc[16][4];
    #pragma unroll
    for (int t = 0; t < 16; t++)
        #pragma unroll
        for (int r = 0; r < 4; r++) oacc[t][r] = 0.0f;

    const int qr0 = qb*64 + w*16 + gid;
    const int qr1 = qr0 + 8;

    for (int kb = 0; kb <= qb; ++kb) {
        cp_wait<0>();          // K/V(kb) landed (issued one iteration ago)
        __syncthreads();       // all warps done with buffer (kb+1)&1's old data
        if (kb + 1 <= qb) {    // prefetch next tile into the other buffer
            load_kv((kb + 1) & 1, kb + 1);
            cp_commit();
        }
        const __half* Ks = fsm + (1 + 2*(kb & 1))*64*FSTR;
        const __half* Vs = fsm + (2 + 2*(kb & 1))*64*FSTR;

        // ---- S = Q K^T ----
        float sacc[8][4];
        #pragma unroll
        for (int j = 0; j < 8; j++)
            #pragma unroll
            for (int r = 0; r < 4; r++) sacc[j][r] = 0.0f;

        #pragma unroll
        for (int kc = 0; kc < 8; kc++) {
            uint32_t af[4];
            ldsm_x4(af, smem_u32(&Qs[(w*16 + a_r)*FSTR + kc*16 + a_c]));
            #pragma unroll
            for (int ng = 0; ng < 4; ng++) {
                uint32_t bf[4];
                ldsm_x4(bf, smem_u32(&Ks[(ng*16 + a_r)*FSTR + kc*16 + a_c]));
                mma_f16_b(sacc[2*ng+0], af, bf[0], bf[2]);
                mma_f16_b(sacc[2*ng+1], af, bf[1], bf[3]);
            }
        }

        // ---- online softmax ----
        const bool diag = (kb == qb);
        float mx0 = -1e30f, mx1 = -1e30f;
        #pragma unroll
        for (int j = 0; j < 8; j++) {
            #pragma unroll
            for (int cc = 0; cc < 2; cc++) {
                const int colg = kb*64 + j*8 + 2*tg + cc;
                float v0 = sacc[j][cc]   * scale;
                float v1 = sacc[j][2+cc] * scale;
                if (diag) {
                    if (colg > qr0) v0 = -1e30f;
                    if (colg > qr1) v1 = -1e30f;
                }
                sacc[j][cc] = v0; sacc[j][2+cc] = v1;
                mx0 = fmaxf(mx0, v0); mx1 = fmaxf(mx1, v1);
            }
        }
        mx0 = fmaxf(mx0, __shfl_xor_sync(0xffffffffu, mx0, 1));
        mx0 = fmaxf(mx0, __shfl_xor_sync(0xffffffffu, mx0, 2));
        mx1 = fmaxf(mx1, __shfl_xor_sync(0xffffffffu, mx1, 1));
        mx1 = fmaxf(mx1, __shfl_xor_sync(0xffffffffu, mx1, 2));

        const float mn0 = fmaxf(m0, mx0), mn1 = fmaxf(m1, mx1);
        const float c0 = __expf(m0 - mn0), c1 = __expf(m1 - mn1);
        float rs0 = 0.0f, rs1 = 0.0f;
        uint32_t ph0[8], ph1[8];
        #pragma unroll
        for (int j = 0; j < 8; j++) {
            const float p00 = __expf(sacc[j][0] - mn0);
            const float p01 = __expf(sacc[j][1] - mn0);
            const float p10 = __expf(sacc[j][2] - mn1);
            const float p11 = __expf(sacc[j][3] - mn1);
            rs0 += p00 + p01; rs1 += p10 + p11;
            ph0[j] = pack_h2(p00, p01);
            ph1[j] = pack_h2(p10, p11);
        }
        rs0 += __shfl_xor_sync(0xffffffffu, rs0, 1);
        rs0 += __shfl_xor_sync(0xffffffffu, rs0, 2);
        rs1 += __shfl_xor_sync(0xffffffffu, rs1, 1);
        rs1 += __shfl_xor_sync(0xffffffffu, rs1, 2);
        l0 = l0*c0 + rs0;  m0 = mn0;
        l1 = l1*c1 + rs1;  m1 = mn1;

        #pragma unroll
        for (int t = 0; t < 16; t++) {
            oacc[t][0] *= c0; oacc[t][1] *= c0;
            oacc[t][2] *= c1; oacc[t][3] *= c1;
        }

        // ---- O += P V ----
        #pragma unroll
        for (int kt = 0; kt < 4; kt++) {
            uint32_t pa[4] = { ph0[2*kt], ph1[2*kt], ph0[2*kt+1], ph1[2*kt+1] };
            #pragma unroll
            for (int ng = 0; ng < 8; ng++) {
                uint32_t bf[4];
                ldsm_x4_t(bf, smem_u32(&Vs[(kt*16 + t_k)*FSTR + ng*16 + t_n]));
                mma_f16_b(oacc[2*ng+0], pa, bf[0], bf[1]);
                mma_f16_b(oacc[2*ng+1], pa, bf[2], bf[3]);
            }
        }
    }

    const float inv0 = 1.0f / l0, inv1 = 1.0f / l1;
    const size_t r0 = rowbase + qr0;
    const size_t r1 = rowbase + qr1;
    #pragma unroll
    for (int t = 0; t < 16; t++) {
        const int col = colbase + t*8 + 2*tg;
        *reinterpret_cast<__half2*>(&O16[r0*HID + col]) =
            __halves2half2(__float2half_rn(oacc[t][0]*inv0),
                           __float2half_rn(oacc[t][1]*inv0));
        *reinterpret_cast<__half2*>(&O16[r1*HID + col]) =
            __halves2half2(__float2half_rn(oacc[t][2]*inv1),
                           __float2half_rn(oacc[t][3]*inv1));
    }
}

// ============================ host side =====================================
extern "C" void kernel_launch(void* const* d_in, const int* in_sizes, int n_in,
                              void* d_out, int out_size)
{
    const float* x     = (const float*)d_in[0];
    const float* wq    = (const float*)d_in[2];
    const float* wk    = (const float*)d_in[3];
    const float* wv    = (const float*)d_in[4];
    const float* wo    = (const float*)d_in[5];
    const float* w_in  = (const float*)d_in[6];
    const float* w_out = (const float*)d_in[7];
    const float* ln1_g = (const float*)d_in[8];
    const float* ln1_b = (const float*)d_in[9];
    const float* ln2_g = (const float*)d_in[10];
    const float* ln2_b = (const float*)d_in[11];
    float* out = (float*)d_out;

    float *h;
    __half *qkv16,*xn16,*att16,*hn16,*ff16;
    __half *wqkv16,*wo16,*win16,*wout16;
    cudaGetSymbolAddress((void**)&qkv16, g_qkv16);
    cudaGetSymbolAddress((void**)&h,  g_h);
    cudaGetSymbolAddress((void**)&xn16, g_xn16);
    cudaGetSymbolAddress((void**)&att16, g_att16);
    cudaGetSymbolAddress((void**)&hn16, g_hn16);
    cudaGetSymbolAddress((void**)&ff16, g_ff16);
    cudaGetSymbolAddress((void**)&wqkv16, g_wqkv16);
    cudaGetSymbolAddress((void**)&wo16, g_wo16);
    cudaGetSymbolAddress((void**)&win16, g_win16);
    cudaGetSymbolAddress((void**)&wout16, g_wout16);

    cudaFuncSetAttribute(tc_gemm<0>, cudaFuncAttributeMaxDynamicSharedMemorySize, GEMM_SMEM);
    cudaFuncSetAttribute(tc_gemm<1>, cudaFuncAttributeMaxDynamicSharedMemorySize, GEMM_SMEM);
    cudaFuncSetAttribute(tc_gemm<2>, cudaFuncAttributeMaxDynamicSharedMemorySize, GEMM_SMEM);
    cudaFuncSetAttribute(flash_kernel, cudaFuncAttributeMaxDynamicSharedMemorySize, FLASH_SMEM);

    // 0. convert weights to RN-fp16
    {
        const int t = 256;
        dim3 gq((HID*HID/4 + t-1)/t, 4);
        convqkv_kernel<<<gq, t>>>(wq, wk, wv, wo, wqkv16, wo16, HID*HID/4);
        dim3 g2((HID*FFD/4 + t-1)/t, 2);
        conv2_kernel<<<g2, t>>>(w_in, win16, w_out, wout16, HID*FFD/4);
    }

    // 1. LN1 -> fp16
    ln_kernel<<<ROWS, 256>>>(x, ln1_g, ln1_b, xn16);

    // 2. fused QKV projection -> fp16
    dim3 gqkv(QKVLD/BN, ROWS/BM);
    tc_gemm<0><<<gqkv, 256, GEMM_SMEM>>>(xn16, wqkv16, nullptr, nullptr, qkv16,
                                         QKVLD, HID);

    // 3. causal flash attention (tensor cores, double-buffered) -> fp16
    dim3 gattn(SEQ/64, BATCH*NHEAD);
    flash_kernel<<<gattn, 128, FLASH_SMEM>>>(qkv16, att16);

    // 4. output projection + residual -> h (fp32)
    dim3 gproj(HID/BN, ROWS/BM);
    tc_gemm<1><<<gproj, 256, GEMM_SMEM>>>(att16, wo16, x, h, nullptr, HID, HID);

    // 5. LN2 -> fp16
    ln_kernel<<<ROWS, 256>>>(h, ln2_g, ln2_b, hn16);

    // 6. FFN up + GELU -> fp16
    dim3 gff1(FFD/BN, ROWS/BM);
    tc_gemm<2><<<gff1, 256, GEMM_SMEM>>>(hn16, win16, nullptr, nullptr, ff16,
                                         FFD, HID);

    // 7. FFN down + residual -> d_out
    dim3 gff2(HID/BN, ROWS/BM);
    tc_gemm<1><<<gff2, 256, GEMM_SMEM>>>(ff16, wout16, h, out, nullptr,
                                         HID, FFD);
}

// round 14
// speedup vs baseline: 1.0394x; 1.0394x over previous
#include <cuda_runtime.h>
#include <cuda_fp16.h>
#include <math.h>
#include <cstdint>

#define BATCH 2
#define SEQ   2048
#define HID   2048
#define NHEAD 16
#define HDIM  128
#define FFD   8192
#define ROWS  (BATCH*SEQ)   // 4096
#define QKVLD (3*HID)       // 6144

// ---------------- scratch ---------------------------------------------------
__device__ __half g_qkv16[(size_t)ROWS*QKVLD];  // packed q|k|v (fp16)
__device__ float g_h [ROWS*HID];
__device__ __half g_xn16[ROWS*HID];
__device__ __half g_att16[ROWS*HID];
__device__ __half g_hn16[ROWS*HID];
__device__ __half g_ff16[(size_t)ROWS*FFD];
__device__ __half g_wqkv16[(size_t)HID*QKVLD];
__device__ __half g_wo16[HID*HID];
__device__ __half g_win16[(size_t)HID*FFD];
__device__ __half g_wout16[(size_t)HID*FFD];

// ============================ helpers ========================================
__device__ __forceinline__ uint32_t smem_u32(const void* p) {
    uint32_t a;
    asm("{ .reg .u64 t; cvta.to.shared.u64 t, %1; cvt.u32.u64 %0, t; }"
        : "=r"(a) : "l"(p));
    return a;
}
__device__ __forceinline__ void cp16(uint32_t dst, const void* src) {
    asm volatile("cp.async.cg.shared.global [%0], [%1], 16;" :: "r"(dst), "l"(src));
}
__device__ __forceinline__ void cp_commit() { asm volatile("cp.async.commit_group;"); }
template<int N> __device__ __forceinline__ void cp_wait() {
    asm volatile("cp.async.wait_group %0;" :: "n"(N));
}
__device__ __forceinline__ void ldsm_x4(uint32_t* r, uint32_t addr) {
    asm volatile("ldmatrix.sync.aligned.m8n8.x4.shared.b16 {%0,%1,%2,%3}, [%4];"
        : "=r"(r[0]), "=r"(r[1]), "=r"(r[2]), "=r"(r[3]) : "r"(addr));
}
__device__ __forceinline__ void ldsm_x4_t(uint32_t* r, uint32_t addr) {
    asm volatile("ldmatrix.sync.aligned.m8n8.x4.trans.shared.b16 {%0,%1,%2,%3}, [%4];"
        : "=r"(r[0]), "=r"(r[1]), "=r"(r[2]), "=r"(r[3]) : "r"(addr));
}
__device__ __forceinline__ void mma_f16(float* c, const uint32_t* a, const uint32_t* b) {
    asm volatile("mma.sync.aligned.m16n8k16.row.col.f32.f16.f16.f32 "
        "{%0,%1,%2,%3}, {%4,%5,%6,%7}, {%8,%9}, {%0,%1,%2,%3};"
        : "+f"(c[0]), "+f"(c[1]), "+f"(c[2]), "+f"(c[3])
        : "r"(a[0]), "r"(a[1]), "r"(a[2]), "r"(a[3]), "r"(b[0]), "r"(b[1]));
}
__device__ __forceinline__ void mma_f16_b(float* c, const uint32_t* a,
                                          uint32_t b0, uint32_t b1) {
    asm volatile("mma.sync.aligned.m16n8k16.row.col.f32.f16.f16.f32 "
        "{%0,%1,%2,%3}, {%4,%5,%6,%7}, {%8,%9}, {%0,%1,%2,%3};"
        : "+f"(c[0]), "+f"(c[1]), "+f"(c[2]), "+f"(c[3])
        : "r"(a[0]), "r"(a[1]), "r"(a[2]), "r"(a[3]), "r"(b0), "r"(b1));
}
__device__ __forceinline__ float gelu_tanh(float x) {
    float x3 = x * x * x;
    float t  = tanhf(0.7978845608028654f * (x + 0.044715f * x3));
    return 0.5f * x * (1.0f + t);
}
__device__ __forceinline__ uint32_t pack_h2(float x, float y) {
    __half2 h = __halves2half2(__float2half_rn(x), __float2half_rn(y));
    return *reinterpret_cast<uint32_t*>(&h);
}

// ============================================================================
// fp16 tensor-core GEMM, fp32 accumulate. BK=32, STG=3 (round-11 best config)
// + fragment double-buffering: kk+1's ldsm issue ahead of kk's MMA block.
// ACT: 0 -> fp16 C, 1 -> fp32 C + Res, 2 -> GELU -> fp16 C
// ============================================================================
#define BM 128
#define BN 128
#define BKH 32
#define LDAH 40
#define LDBH 136
#define ASZH (BM*LDAH)
#define BSZH (BKH*LDBH)
#define STG 3
#define STAGEH (ASZH + BSZH)
#define GEMM_SMEM (STG*STAGEH*2)    // 56832 bytes -> 2 CTAs/SM

template<int ACT>
__global__ __launch_bounds__(256, 2) void tc_gemm(
    const __half* __restrict__ A16,
    const __half* __restrict__ B16,
    const float* __restrict__ Res, float* __restrict__ Cf,
    __half* __restrict__ C16,
    int N_, int K)
{
    extern __shared__ __align__(16) __half smem[];

    const int tid  = threadIdx.x;
    const int wid  = tid >> 5;
    const int lane = tid & 31;
    const int gid  = lane >> 2;
    const int tg   = lane & 3;
    const int wm   = wid & 3;
    const int wn   = wid >> 2;
    const int bm = blockIdx.y * BM;
    const int bn = blockIdx.x * BN;
    const int nK = K / BKH;

    const int a_m = lane & 15;
    const int a_k = (lane >> 4) * 8;
    const int b_k = ((lane >> 3) & 1) * 8 + (lane & 7);
    const int b_n = (lane >> 4) * 8;

    auto load_stage = [&](int s, int kt) {
        const int k0 = kt * BKH;
        __half* As = smem + s*STAGEH;
        __half* Bs = As + ASZH;
        #pragma unroll
        for (int i = 0; i < 2; i++) {
            const int c  = tid + 256*i;
            const int ar = c >> 2, ak = (c & 3) << 3;
            cp16(smem_u32(&As[ar*LDAH + ak]), &A16[(size_t)(bm + ar)*K + k0 + ak]);
            const int bk = c >> 4, bnn = (c & 15) << 3;
            cp16(smem_u32(&Bs[bk*LDBH + bnn]), &B16[(size_t)(k0 + bk)*N_ + bn + bnn]);
        }
        cp_commit();
    };

    float acc[2][8][4];
    #pragma unroll
    for (int mt = 0; mt < 2; mt++)
        #pragma unroll
        for (int nt = 0; nt < 8; nt++)
            #pragma unroll
            for (int r = 0; r < 4; r++) acc[mt][nt][r] = 0.0f;

    load_stage(0, 0);
    load_stage(1, 1);

    // double-buffered fragments
    uint32_t aF[2][2][4];   // [buf][mt][regs]
    uint32_t bF[2][4][4];   // [buf][ng][regs]

    auto load_frags = [&](int buf, const __half* As, const __half* Bs, int kk) {
        #pragma unroll
        for (int mt = 0; mt < 2; mt++) {
            const int mrow = wm*32 + mt*16 + a_m;
            ldsm_x4(aF[buf][mt], smem_u32(&As[mrow*LDAH + kk*16 + a_k]));
        }
        #pragma unroll
        for (int ng = 0; ng < 4; ng++) {
            const int noff = wn*64 + ng*16 + b_n;
            ldsm_x4_t(bF[buf][ng], smem_u32(&Bs[(kk*16 + b_k)*LDBH + noff]));
        }
    };

    for (int kt = 0; kt < nK; kt++) {
        cp_wait<1>();
        __syncthreads();
        if (kt + STG - 1 < nK)
            load_stage((kt + STG - 1) % STG, kt + STG - 1);

        const int s = kt % STG;
        const __half* As = smem + s*STAGEH;
        const __half* Bs = As + ASZH;

        load_frags(0, As, Bs, 0);       // kk=0 fragments (exposed)
        load_frags(1, As, Bs, 1);       // kk=1 fragments issue ahead of MMAs

        #pragma unroll
        for (int kk = 0; kk < 2; kk++) {
            #pragma unroll
            for (int mt = 0; mt < 2; mt++)
                #pragma unroll
                for (int nt = 0; nt < 8; nt++)
                    mma_f16(acc[mt][nt], aF[kk][mt], &bF[kk][nt >> 1][(nt & 1) * 2]);
        }
    }

    #pragma unroll
    for (int mt = 0; mt < 2; mt++) {
        #pragma unroll
        for (int half_ = 0; half_ < 2; half_++) {
            const int r = bm + wm*32 + mt*16 + gid + half_*8;
            #pragma unroll
            for (int nt = 0; nt < 8; nt++) {
                const int cc = bn + wn*64 + nt*8 + tg*2;
                float v0 = acc[mt][nt][half_*2 + 0];
                float v1 = acc[mt][nt][half_*2 + 1];
                if (ACT == 0) {
                    *reinterpret_cast<__half2*>(&C16[(size_t)r*N_ + cc]) =
                        __halves2half2(__float2half_rn(v0), __float2half_rn(v1));
                } else if (ACT == 2) {
                    v0 = gelu_tanh(v0); v1 = gelu_tanh(v1);
                    *reinterpret_cast<__half2*>(&C16[(size_t)r*N_ + cc]) =
                        __halves2half2(__float2half_rn(v0), __float2half_rn(v1));
                } else {
                    const float2 rr = *reinterpret_cast<const float2*>(&Res[(size_t)r*N_ + cc]);
                    float2 o; o.x = v0 + rr.x; o.y = v1 + rr.y;
                    *reinterpret_cast<float2*>(&Cf[(size_t)r*N_ + cc]) = o;
                }
            }
        }
    }
}

// ------------- weight conversion: fp32 -> RN fp16 ---------------------------
__global__ void convqkv_kernel(const float* __restrict__ wq,
                               const float* __restrict__ wk,
                               const float* __restrict__ wv,
                               const float* __restrict__ wo,
                               __half* __restrict__ qkv16,
                               __half* __restrict__ wo16,
                               int n4)
{
    const int i = blockIdx.x*blockDim.x + threadIdx.x;
    if (i >= n4) return;
    const int y = blockIdx.y;
    const float* in = (y == 0) ? wq : (y == 1) ? wk : (y == 2) ? wv : wo;
    const int e   = i * 4;
    const int row = e >> 11;
    const int col = e & 2047;
    float4 v = reinterpret_cast<const float4*>(in)[i];
    __half2 p0 = __halves2half2(__float2half_rn(v.x), __float2half_rn(v.y));
    __half2 p1 = __halves2half2(__float2half_rn(v.z), __float2half_rn(v.w));
    __half* dst; size_t o;
    if (y < 3) { dst = qkv16; o = (size_t)row*QKVLD + y*HID + col; }
    else       { dst = wo16;  o = (size_t)row*HID + col; }
    reinterpret_cast<__half2*>(dst + o)[0] = p0;
    reinterpret_cast<__half2*>(dst + o)[1] = p1;
}
__global__ void conv2_kernel(const float* __restrict__ w0, __half* o0,
                             const float* __restrict__ w1, __half* o1,
                             int n4)
{
    const float* in = blockIdx.y ? w1 : w0;
    __half* dst = blockIdx.y ? o1 : o0;
    const int i = blockIdx.x*blockDim.x + threadIdx.x;
    if (i >= n4) return;
    float4 v = reinterpret_cast<const float4*>(in)[i];
    reinterpret_cast<__half2*>(dst)[2*i+0] =
        __halves2half2(__float2half_rn(v.x), __float2half_rn(v.y));
    reinterpret_cast<__half2*>(dst)[2*i+1] =
        __halves2half2(__float2half_rn(v.z), __float2half_rn(v.w));
}

// ---------------- LayerNorm -> fp16 output ----------------------------------
__global__ void ln_kernel(const float* __restrict__ x,
                          const float* __restrict__ g,
                          const float* __restrict__ b,
                          __half* __restrict__ o16)
{
    const int row = blockIdx.x;
    const int tid = threadIdx.x;
    const float* xr = x + (size_t)row * HID;

    float4 v0 = reinterpret_cast<const float4*>(xr)[tid];
    float4 v1 = reinterpret_cast<const float4*>(xr)[tid + 256];

    __shared__ float red[8];

    float s = v0.x+v0.y+v0.z+v0.w + v1.x+v1.y+v1.z+v1.w;
    #pragma unroll
    for (int o = 16; o > 0; o >>= 1) s += __shfl_xor_sync(0xffffffffu, s, o);
    if ((tid & 31) == 0) red[tid >> 5] = s;
    __syncthreads();
    float mu = (red[0]+red[1]+red[2]+red[3]+red[4]+red[5]+red[6]+red[7]) * (1.0f/HID);
    __syncthreads();

    float d0x=v0.x-mu, d0y=v0.y-mu, d0z=v0.z-mu, d0w=v0.w-mu;
    float d1x=v1.x-mu, d1y=v1.y-mu, d1z=v1.z-mu, d1w=v1.w-mu;
    float sq = d0x*d0x+d0y*d0y+d0z*d0z+d0w*d0w + d1x*d1x+d1y*d1y+d1z*d1z+d1w*d1w;
    #pragma unroll
    for (int o = 16; o > 0; o >>= 1) sq += __shfl_xor_sync(0xffffffffu, sq, o);
    if ((tid & 31) == 0) red[tid >> 5] = sq;
    __syncthreads();
    float var = (red[0]+red[1]+red[2]+red[3]+red[4]+red[5]+red[6]+red[7]) * (1.0f/HID);
    float rstd = rsqrtf(var + 1e-5f);

    float4 g0 = reinterpret_cast<const float4*>(g)[tid];
    float4 g1 = reinterpret_cast<const float4*>(g)[tid + 256];
    float4 b0 = reinterpret_cast<const float4*>(b)[tid];
    float4 b1 = reinterpret_cast<const float4*>(b)[tid + 256];

    const size_t base = (size_t)row * HID;
    reinterpret_cast<__half2*>(o16 + base)[tid*2+0] = __halves2half2(
        __float2half_rn(d0x*rstd*g0.x + b0.x), __float2half_rn(d0y*rstd*g0.y + b0.y));
    reinterpret_cast<__half2*>(o16 + base)[tid*2+1] = __halves2half2(
        __float2half_rn(d0z*rstd*g0.z + b0.z), __float2half_rn(d0w*rstd*g0.w + b0.w));
    reinterpret_cast<__half2*>(o16 + base)[(tid+256)*2+0] = __halves2half2(
        __float2half_rn(d1x*rstd*g1.x + b1.x), __float2half_rn(d1y*rstd*g1.y + b1.y));
    reinterpret_cast<__half2*>(o16 + base)[(tid+256)*2+1] = __halves2half2(
        __float2half_rn(d1z*rstd*g1.z + b1.z), __float2half_rn(d1w*rstd*g1.w + b1.w));
}

// ---------------- Flash attention: fp16 mma.sync (round-11 config) ----------
#define FSTR 136
#define FLASH_SMEM (3*64*FSTR*2)

__global__ __launch_bounds__(128, 3) void flash_kernel(
    const __half* __restrict__ QKV,
    __half* __restrict__ O16)
{
    extern __shared__ __align__(16) __half fsm[];
    __half* Qs = fsm;
    __half* Ks = Qs + 64*FSTR;
    __half* Vs = Ks + 64*FSTR;

    const int tid = threadIdx.x;
    const int w   = tid >> 5;
    const int lane = tid & 31;
    const int gid = lane >> 2;
    const int tg  = lane & 3;
    const int bh = blockIdx.y;
    const int b  = bh >> 4;
    const int h  = bh & 15;
    const int qb = blockIdx.x;
    const size_t rowbase = (size_t)b * SEQ;
    const int colbase = h * HDIM;
    const float scale = 0.088388347648318447f;

    const int a_r = lane & 15;
    const int a_c = (lane >> 4) * 8;
    const int t_k = ((lane >> 3) & 1) * 8 + (lane & 7);
    const int t_n = (lane >> 4) * 8;

    #pragma unroll
    for (int it = 0; it < 8; ++it) {
        int idx = it*128 + tid;
        int r = idx >> 4;
        int c8 = (idx & 15) << 3;
        cp16(smem_u32(&Qs[r*FSTR + c8]),
             &QKV[(rowbase + qb*64 + r)*(size_t)QKVLD + colbase + c8]);
    }
    cp_commit();

    float m0 = -1e30f, m1 = -1e30f, l0 = 0.0f, l1 = 0.0f;
    float oacc[16][4];
    #pragma unroll
    for (int t = 0; t < 16; t++)
        #pragma unroll
        for (int r = 0; r < 4; r++) oacc[t][r] = 0.0f;

    const int qr0 = qb*64 + w*16 + gid;
    const int qr1 = qr0 + 8;

    for (int kb = 0; kb <= qb; ++kb) {
        __syncthreads();
        #pragma unroll
        for (int it = 0; it < 8; ++it) {
            int idx = it*128 + tid;
            int r = idx >> 4;
            int c8 = (idx & 15) << 3;
            const size_t grow = (rowbase + kb*64 + r)*(size_t)QKVLD + colbase + c8;
            cp16(smem_u32(&Ks[r*FSTR + c8]), &QKV[grow + HID]);
            cp16(smem_u32(&Vs[r*FSTR + c8]), &QKV[grow + 2*HID]);
        }
        cp_commit();
        cp_wait<0>();
        __syncthreads();

        float sacc[8][4];
        #pragma unroll
        for (int j = 0; j < 8; j++)
            #pragma unroll
            for (int r = 0; r < 4; r++) sacc[j][r] = 0.0f;

        #pragma unroll
        for (int kc = 0; kc < 8; kc++) {
            uint32_t af[4];
            ldsm_x4(af, smem_u32(&Qs[(w*16 + a_r)*FSTR + kc*16 + a_c]));
            #pragma unroll
            for (int ng = 0; ng < 4; ng++) {
                uint32_t bf[4];
                ldsm_x4(bf, smem_u32(&Ks[(ng*16 + a_r)*FSTR + kc*16 + a_c]));
                mma_f16_b(sacc[2*ng+0], af, bf[0], bf[2]);
                mma_f16_b(sacc[2*ng+1], af, bf[1], bf[3]);
            }
        }

        const bool diag = (kb == qb);
        float mx0 = -1e30f, mx1 = -1e30f;
        #pragma unroll
        for (int j = 0; j < 8; j++) {
            #pragma unroll
            for (int cc = 0; cc < 2; cc++) {
                const int colg = kb*64 + j*8 + 2*tg + cc;
                float v0 = sacc[j][cc]   * scale;
                float v1 = sacc[j][2+cc] * scale;
                if (diag) {
                    if (colg > qr0) v0 = -1e30f;
                    if (colg > qr1) v1 = -1e30f;
                }
                sacc[j][cc] = v0; sacc[j][2+cc] = v1;
                mx0 = fmaxf(mx0, v0); mx1 = fmaxf(mx1, v1);
            }
        }
        mx0 = fmaxf(mx0, __shfl_xor_sync(0xffffffffu, mx0, 1));
        mx0 = fmaxf(mx0, __shfl_xor_sync(0xffffffffu, mx0, 2));
        mx1 = fmaxf(mx1, __shfl_xor_sync(0xffffffffu, mx1, 1));
        mx1 = fmaxf(mx1, __shfl_xor_sync(0xffffffffu, mx1, 2));

        const float mn0 = fmaxf(m0, mx0), mn1 = fmaxf(m1, mx1);
        const float c0 = __expf(m0 - mn0), c1 = __expf(m1 - mn1);
        float rs0 = 0.0f, rs1 = 0.0f;
        uint32_t ph0[8], ph1[8];
        #pragma unroll
        for (int j = 0; j < 8; j++) {
            const float p00 = __expf(sacc[j][0] - mn0);
            const float p01 = __expf(sacc[j][1] - mn0);
            const float p10 = __expf(sacc[j][2] - mn1);
            const float p11 = __expf(sacc[j][3] - mn1);
            rs0 += p00 + p01; rs1 += p10 + p11;
            ph0[j] = pack_h2(p00, p01);
            ph1[j] = pack_h2(p10, p11);
        }
        rs0 += __shfl_xor_sync(0xffffffffu, rs0, 1);
        rs0 += __shfl_xor_sync(0xffffffffu, rs0, 2);
        rs1 += __shfl_xor_sync(0xffffffffu, rs1, 1);
        rs1 += __shfl_xor_sync(0xffffffffu, rs1, 2);
        l0 = l0*c0 + rs0;  m0 = mn0;
        l1 = l1*c1 + rs1;  m1 = mn1;

        #pragma unroll
        for (int t = 0; t < 16; t++) {
            oacc[t][0] *= c0; oacc[t][1] *= c0;
            oacc[t][2] *= c1; oacc[t][3] *= c1;
        }

        #pragma unroll
        for (int kt = 0; kt < 4; kt++) {
            uint32_t pa[4] = { ph0[2*kt], ph1[2*kt], ph0[2*kt+1], ph1[2*kt+1] };
            #pragma unroll
            for (int ng = 0; ng < 8; ng++) {
                uint32_t bf[4];
                ldsm_x4_t(bf, smem_u32(&Vs[(kt*16 + t_k)*FSTR + ng*16 + t_n]));
                mma_f16_b(oacc[2*ng+0], pa, bf[0], bf[1]);
                mma_f16_b(oacc[2*ng+1], pa, bf[2], bf[3]);
            }
        }
    }

    const float inv0 = 1.0f / l0, inv1 = 1.0f / l1;
    const size_t r0 = rowbase + qr0;
    const size_t r1 = rowbase + qr1;
    #pragma unroll
    for (int t = 0; t < 16; t++) {
        const int col = colbase + t*8 + 2*tg;
        *reinterpret_cast<__half2*>(&O16[r0*HID + col]) =
            __halves2half2(__float2half_rn(oacc[t][0]*inv0),
                           __float2half_rn(oacc[t][1]*inv0));
        *reinterpret_cast<__half2*>(&O16[r1*HID + col]) =
            __halves2half2(__float2half_rn(oacc[t][2]*inv1),
                           __float2half_rn(oacc[t][3]*inv1));
    }
}

// ============================ host side =====================================
extern "C" void kernel_launch(void* const* d_in, const int* in_sizes, int n_in,
                              void* d_out, int out_size)
{
    const float* x     = (const float*)d_in[0];
    const float* wq    = (const float*)d_in[2];
    const float* wk    = (const float*)d_in[3];
    const float* wv    = (const float*)d_in[4];
    const float* wo    = (const float*)d_in[5];
    const float* w_in  = (const float*)d_in[6];
    const float* w_out = (const float*)d_in[7];
    const float* ln1_g = (const float*)d_in[8];
    const float* ln1_b = (const float*)d_in[9];
    const float* ln2_g = (const float*)d_in[10];
    const float* ln2_b = (const float*)d_in[11];
    float* out = (float*)d_out;

    float *h;
    __half *qkv16,*xn16,*att16,*hn16,*ff16;
    __half *wqkv16,*wo16,*win16,*wout16;
    cudaGetSymbolAddress((void**)&qkv16, g_qkv16);
    cudaGetSymbolAddress((void**)&h,  g_h);
    cudaGetSymbolAddress((void**)&xn16, g_xn16);
    cudaGetSymbolAddress((void**)&att16, g_att16);
    cudaGetSymbolAddress((void**)&hn16, g_hn16);
    cudaGetSymbolAddress((void**)&ff16, g_ff16);
    cudaGetSymbolAddress((void**)&wqkv16, g_wqkv16);
    cudaGetSymbolAddress((void**)&wo16, g_wo16);
    cudaGetSymbolAddress((void**)&win16, g_win16);
    cudaGetSymbolAddress((void**)&wout16, g_wout16);

    cudaFuncSetAttribute(tc_gemm<0>, cudaFuncAttributeMaxDynamicSharedMemorySize, GEMM_SMEM);
    cudaFuncSetAttribute(tc_gemm<1>, cudaFuncAttributeMaxDynamicSharedMemorySize, GEMM_SMEM);
    cudaFuncSetAttribute(tc_gemm<2>, cudaFuncAttributeMaxDynamicSharedMemorySize, GEMM_SMEM);
    cudaFuncSetAttribute(flash_kernel, cudaFuncAttributeMaxDynamicSharedMemorySize, FLASH_SMEM);

    // 0. convert weights to RN-fp16
    {
        const int t = 256;
        dim3 gq((HID*HID/4 + t-1)/t, 4);
        convqkv_kernel<<<gq, t>>>(wq, wk, wv, wo, wqkv16, wo16, HID*HID/4);
        dim3 g2((HID*FFD/4 + t-1)/t, 2);
        conv2_kernel<<<g2, t>>>(w_in, win16, w_out, wout16, HID*FFD/4);
    }

    // 1. LN1 -> fp16
    ln_kernel<<<ROWS, 256>>>(x, ln1_g, ln1_b, xn16);

    // 2. fused QKV projection -> fp16
    dim3 gqkv(QKVLD/BN, ROWS/BM);
    tc_gemm<0><<<gqkv, 256, GEMM_SMEM>>>(xn16, wqkv16, nullptr, nullptr, qkv16,
                                         QKVLD, HID);

    // 3. causal flash attention (tensor cores) -> fp16
    dim3 gattn(SEQ/64, BATCH*NHEAD);
    flash_kernel<<<gattn, 128, FLASH_SMEM>>>(qkv16, att16);

    // 4. output projection + residual -> h (fp32)
    dim3 gproj(HID/BN, ROWS/BM);
    tc_gemm<1><<<gproj, 256, GEMM_SMEM>>>(att16, wo16, x, h, nullptr, HID, HID);

    // 5. LN2 -> fp16
    ln_kernel<<<ROWS, 256>>>(h, ln2_g, ln2_b, hn16);

    // 6. FFN up + GELU -> fp16
    dim3 gff1(FFD/BN, ROWS/BM);
    tc_gemm<2><<<gff1, 256, GEMM_SMEM>>>(hn16, win16, nullptr, nullptr, ff16,
                                         FFD, HID);

    // 7. FFN down + residual -> d_out
    dim3 gff2(HID/BN, ROWS/BM);
    tc_gemm<1><<<gff2, 256, GEMM_SMEM>>>(ff16, wout16, h, out, nullptr,
                                         HID, FFD);
}